// round 2
// baseline (speedup 1.0000x reference)
#include <cuda_runtime.h>
#include <math.h>

#define S 2048
#define D 1024
#define NI 13
#define NO 130
#define LN_EPS 1e-5f
#define TAIL_EPS 1e-7f
#define K1_ROWS 16
// dynamic smem: xs[16*1024] + Wt[64*132] + ps[16*132] + mu[16] + rs[16]
#define K1_SMEM ((K1_ROWS*D + 64*132 + K1_ROWS*132 + 2*K1_ROWS) * 4)

// Scratch (allocation-free rule: __device__ globals)
__device__ float4 g_lin[NI * S];   // rot.x, rot.y, state0.x, state0.y  (linear)
__device__ float4 g_ang[NI * S];   // rot.x, rot.y, state0.x, state0.y  (angular)
__device__ int    g_tcut[NI * S];

__device__ __forceinline__ float sp(float x) {
    // numerically stable softplus, matches jax.nn.softplus in fp32
    return (x > 0.f) ? x + log1pf(expf(-x)) : log1pf(expf(x));
}

// ---------------------------------------------------------------------------
// Kernel 1: fused LayerNorm + GEMM (2048x1024 @ 1024x130) + parameter derivation
// blockDim (32, 8), 16 rows per block, 128 blocks
// ---------------------------------------------------------------------------
__global__ void __launch_bounds__(256, 1)
k1(const float* __restrict__ x, const float* __restrict__ minp,
   const float* __restrict__ gamma, const float* __restrict__ beta,
   const float* __restrict__ W, const float* __restrict__ bias,
   float* __restrict__ out)
{
    extern __shared__ float sm[];
    float* xs = sm;                        // [16][1024] normalized activations
    float* Wt = xs + K1_ROWS * D;          // [64][132]  W k-chunk tile (padded)
    float* ps = Wt + 64 * 132;             // [16][132]  p = xn @ W + b
    float* mu = ps + K1_ROWS * 132;        // [16]
    float* rs = mu + K1_ROWS;              // [16]

    const int tx = threadIdx.x, ty = threadIdx.y;
    const int tid = ty * 32 + tx;
    const int r0 = blockIdx.x * K1_ROWS;

    // ---- load 16 rows of x into smem ----
    const float* xb = x + (size_t)r0 * D;
    for (int idx = tid; idx < K1_ROWS * D; idx += 256) xs[idx] = xb[idx];
    __syncthreads();

    // ---- LayerNorm stats: warp ty reduces rows 2ty, 2ty+1 ----
    #pragma unroll
    for (int rr = 0; rr < 2; ++rr) {
        int r = ty * 2 + rr;
        float s1 = 0.f, s2 = 0.f;
        const float* row = xs + r * D;
        for (int k = tx; k < D; k += 32) { float v = row[k]; s1 += v; s2 += v * v; }
        #pragma unroll
        for (int o = 16; o; o >>= 1) {
            s1 += __shfl_xor_sync(0xffffffffu, s1, o);
            s2 += __shfl_xor_sync(0xffffffffu, s2, o);
        }
        if (tx == 0) {
            float m = s1 * (1.f / D);
            float var = s2 * (1.f / D) - m * m;
            mu[r] = m;
            rs[r] = rsqrtf(var + LN_EPS);
        }
    }
    __syncthreads();

    // ---- normalize in place (apply gamma/beta) ----
    for (int idx = tid; idx < K1_ROWS * D; idx += 256) {
        int r = idx >> 10, k = idx & (D - 1);
        xs[idx] = (xs[idx] - mu[r]) * rs[r] * gamma[k] + beta[k];
    }
    __syncthreads();

    // ---- GEMM: thread (tx,ty) owns rows {ty, ty+8}, cols {tx+32c} ----
    float acc[2][5];
    #pragma unroll
    for (int a = 0; a < 2; ++a)
        #pragma unroll
        for (int c = 0; c < 5; ++c) acc[a][c] = 0.f;

    for (int kc = 0; kc < D; kc += 64) {
        for (int idx = tid; idx < 64 * 132; idx += 256) {
            int kk = idx / 132, o = idx - kk * 132;
            Wt[idx] = (o < NO) ? W[(kc + kk) * NO + o] : 0.f;
        }
        __syncthreads();
        const float* x0 = xs + ty * D + kc;
        const float* x1 = xs + (ty + 8) * D + kc;
        #pragma unroll 8
        for (int kk = 0; kk < 64; ++kk) {
            float a0 = x0[kk], a1 = x1[kk];        // LDS broadcast within warp
            const float* wr = Wt + kk * 132 + tx;  // conflict-free
            #pragma unroll
            for (int c = 0; c < 5; ++c) {
                float w = wr[32 * c];
                acc[0][c] += a0 * w;
                acc[1][c] += a1 * w;
            }
        }
        __syncthreads();
    }
    #pragma unroll
    for (int a = 0; a < 2; ++a) {
        int r = ty + 8 * a;
        #pragma unroll
        for (int c = 0; c < 5; ++c) {
            int o = tx + 32 * c;
            if (o < NO) ps[r * 132 + o] = acc[a][c] + bias[o];
        }
    }
    __syncthreads();

    // ---- derive damped-sinusoid params: 16 rows x 13 imus = 208 jobs ----
    if (tid < K1_ROWS * NI) {
        int il = tid / NI, m = tid - il * NI;
        int i = r0 + il;
        const float* p = ps + il * 132;
        float p0 = p[0 * 13 + m], p1 = p[1 * 13 + m];
        float p2 = p[2 * 13 + m], p3 = p[3 * 13 + m];
        float c   = p[4 * 13 + m], cth   = p[5 * 13 + m];
        float phi = p[6 * 13 + m], phith = p[7 * 13 + m];
        float nb  = p[8 * 13 + m], p9    = p[9 * 13 + m];

        // outputs that don't need the double sum
        out[m * S + i]          = minp[0] + nb;   // kin added later by k2
        out[NI * S + m * S + i] = sp(p9);         // noise_std

        // linear part: omega = sqrt(softplus(p0)), d = softplus(p1)
        float dh = 0.5f * sp(p1);
        float om = sqrtf(sp(p0));
        float e  = expf(-dh);
        float4 L;
        L.x = e * cosf(om);  L.y = e * sinf(om);
        L.z = c * cosf(phi); L.w = c * sinf(phi);
        float em = -expm1f(-dh);  // 1 - e^{-dh}, accurate for small dh
        // t_cut: total geometric tail |c| e^{-dh t}/(1-e^{-dh}) <= TAIL_EPS
        float tl = ceilf(logf(fmaxf(fabsf(c), 1e-30f) / (TAIL_EPS * em)) / dh);

        // angular part
        float dha = 0.5f * sp(p3);
        float oma = sqrtf(sp(p2));
        float ea  = expf(-dha);
        float4 A;
        A.x = ea * cosf(oma);    A.y = ea * sinf(oma);
        A.z = cth * cosf(phith); A.w = cth * sinf(phith);
        float ema = -expm1f(-dha);
        float ta = ceilf(logf(fmaxf(fabsf(cth), 1e-30f) / (TAIL_EPS * ema)) / dha);

        float tmax = fminf(fmaxf(fmaxf(tl, ta), 0.f), (float)S);
        g_lin[m * S + i]  = L;
        g_ang[m * S + i]  = A;
        g_tcut[m * S + i] = (int)tmax;
    }
}

// ---------------------------------------------------------------------------
// Kernel 2: truncated damped-sinusoid scatter via complex-rotation recurrence.
// grid (16 bands, 13 imus), 128 threads. Thread = source row i, walks
// j = i .. min(S-1, i+tcut), accumulating Im[state] into a shared kin[S]
// via shared-memory atomicAdd.
//
// NOTE: a plain `kin[j] += v` RMW here is a cross-lane race: lane L at
// iteration t+1 touches the address lane L+1 wrote at iteration t, and ptxas
// hoists the LDS above the prior STS. atomicAdd makes the accumulation
// order-independent; addresses are distinct per instruction so there is no
// serialization (ATOMS spread-addr ~2 cyc/lane), off the 8-cyc FFMA chain.
// ---------------------------------------------------------------------------
__global__ void __launch_bounds__(128, 2)
k2(float* __restrict__ out)
{
    __shared__ float kin[S];   // 8 KB
    const int tid  = threadIdx.x;
    const int band = blockIdx.x, m = blockIdx.y;

    for (int idx = tid; idx < S; idx += 128) kin[idx] = 0.f;
    __syncthreads();

    const int i  = band * 128 + tid;
    const int gi = m * S + i;
    const float4 L = g_lin[gi];
    const float4 A = g_ang[gi];
    const int   tc = g_tcut[gi];

    float sxl = L.z, syl = L.w;
    float sxa = A.z, sya = A.w;
    const int jend = min(S, i + tc + 1);
    for (int j = i; j < jend; ++j) {
        atomicAdd(&kin[j], syl + sya);
        float nxl = L.x * sxl - L.y * syl;
        float nyl = L.x * syl + L.y * sxl;
        sxl = nxl; syl = nyl;
        float nxa = A.x * sxa - A.y * sya;
        float nya = A.x * sya + A.y * sxa;
        sxa = nxa; sya = nya;
    }
    __syncthreads();

    // merge into out (cross-block via global atomics); only j >= band*128
    // can be nonzero since sources start at i >= band*128
    float* orow = out + m * S;
    for (int j = band * 128 + tid; j < S; j += 128) {
        atomicAdd(orow + j, kin[j]);
    }
}

extern "C" void kernel_launch(void* const* d_in, const int* in_sizes, int n_in,
                              void* d_out, int out_size)
{
    const float* x     = (const float*)d_in[0];  // (1, 2048, 1024)
    const float* minp  = (const float*)d_in[1];  // (1,)
    const float* gamma = (const float*)d_in[2];  // (1024,)
    const float* beta  = (const float*)d_in[3];  // (1024,)
    const float* W     = (const float*)d_in[4];  // (1024, 130)
    const float* b     = (const float*)d_in[5];  // (130,)
    float* out = (float*)d_out;                  // (13,2048) out ++ (13,2048) noise_std

    cudaFuncSetAttribute(k1, cudaFuncAttributeMaxDynamicSharedMemorySize, K1_SMEM);

    k1<<<S / K1_ROWS, dim3(32, 8), K1_SMEM>>>(x, minp, gamma, beta, W, b, out);
    k2<<<dim3(S / 128, NI), 128>>>(out);
}

// round 3
// speedup vs baseline: 2.0027x; 2.0027x over previous
#include <cuda_runtime.h>
#include <math.h>

#define S 2048
#define D 1024
#define NI 13
#define NO 130
#define LN_EPS 1e-5f
#define TAIL_EPS 1e-7f

// k1 dynamic smem: xs2 float2[8][1024] + Wt2 float2[2][64][132] + ps float[16][132]
#define XS2_F2   (8 * 1024)
#define WT2_F2   (64 * 132)
#define K1_SMEM  (XS2_F2 * 8 + 2 * WT2_F2 * 8 + 16 * 132 * 4)   // 209152 B

// Scratch (allocation-free rule: __device__ globals)
__device__ float4 g_lin[NI * S];   // rot.x, rot.y, state0.x, state0.y  (linear)
__device__ float4 g_ang[NI * S];   // rot.x, rot.y, state0.x, state0.y  (angular)
__device__ int    g_tcut[NI * S];

__device__ __forceinline__ float sp(float x) {
    return (x > 0.f) ? x + log1pf(expf(-x)) : log1pf(expf(x));
}

__device__ __forceinline__ void ffma2(unsigned long long& acc,
                                      unsigned long long a, unsigned long long w) {
    asm("fma.rn.f32x2 %0, %1, %2, %0;" : "+l"(acc) : "l"(a), "l"(w));
}
__device__ __forceinline__ void unpack2(float& lo, float& hi, unsigned long long v) {
    asm("mov.b64 {%0, %1}, %2;" : "=f"(lo), "=f"(hi) : "l"(v));
}

// ---------------------------------------------------------------------------
// Kernel 1: fused LayerNorm + GEMM (2048x1024 @ 1024x130) + parameter derivation
// block (32,8)=256 threads, 16 rows/block, 128 blocks.
// Rows packed pairwise into f32x2; W pre-duplicated {w,w}; double-buffered W.
// ---------------------------------------------------------------------------
__global__ void __launch_bounds__(256, 1)
k1(const float* __restrict__ x, const float* __restrict__ minp,
   const float* __restrict__ gamma, const float* __restrict__ beta,
   const float* __restrict__ W, const float* __restrict__ bias,
   float* __restrict__ out)
{
    extern __shared__ char smraw[];
    float2* xs2 = (float2*)smraw;                       // [8][1024]  {row ty, row ty+8}
    float2* Wt2 = xs2 + XS2_F2;                          // [2][64][132] duplicated
    float*  ps  = (float*)(Wt2 + 2 * WT2_F2);            // [16][132]

    const int tx = threadIdx.x, ty = threadIdx.y;
    const int tid = ty * 32 + tx;
    const int r0 = blockIdx.x * 16;

    // ---- LayerNorm stats for rows (r0+ty, r0+ty+8), direct from global ----
    const float4* xr0 = (const float4*)(x + (size_t)(r0 + ty) * D);
    const float4* xr1 = (const float4*)(x + (size_t)(r0 + ty + 8) * D);
    float s1 = 0.f, s2 = 0.f, u1 = 0.f, u2 = 0.f;
    #pragma unroll
    for (int it = 0; it < 8; ++it) {
        float4 a = xr0[it * 32 + tx];
        float4 b = xr1[it * 32 + tx];
        s1 += a.x + a.y + a.z + a.w;
        s2 += a.x * a.x + a.y * a.y + a.z * a.z + a.w * a.w;
        u1 += b.x + b.y + b.z + b.w;
        u2 += b.x * b.x + b.y * b.y + b.z * b.z + b.w * b.w;
    }
    #pragma unroll
    for (int o = 16; o; o >>= 1) {
        s1 += __shfl_xor_sync(0xffffffffu, s1, o);
        s2 += __shfl_xor_sync(0xffffffffu, s2, o);
        u1 += __shfl_xor_sync(0xffffffffu, u1, o);
        u2 += __shfl_xor_sync(0xffffffffu, u2, o);
    }
    const float mu0 = s1 * (1.f / D);
    const float rs0 = rsqrtf(s2 * (1.f / D) - mu0 * mu0 + LN_EPS);
    const float mu1 = u1 * (1.f / D);
    const float rs1 = rsqrtf(u2 * (1.f / D) - mu1 * mu1 + LN_EPS);

    // ---- normalize (second pass, L2-hot) and pack rows pairwise ----
    const float4* g4p = (const float4*)gamma;
    const float4* b4p = (const float4*)beta;
    float2* xrow = xs2 + ty * 1024;
    #pragma unroll
    for (int it = 0; it < 8; ++it) {
        int e = it * 32 + tx;
        float4 a = xr0[e], b = xr1[e];
        float4 g = g4p[e], be = b4p[e];
        int k = e * 4;
        xrow[k + 0] = make_float2((a.x - mu0) * rs0 * g.x + be.x, (b.x - mu1) * rs1 * g.x + be.x);
        xrow[k + 1] = make_float2((a.y - mu0) * rs0 * g.y + be.y, (b.y - mu1) * rs1 * g.y + be.y);
        xrow[k + 2] = make_float2((a.z - mu0) * rs0 * g.z + be.z, (b.z - mu1) * rs1 * g.z + be.z);
        xrow[k + 3] = make_float2((a.w - mu0) * rs0 * g.w + be.w, (b.w - mu1) * rs1 * g.w + be.w);
    }

    // ---- GEMM: acc[c] f32x2 = {row ty, row ty+8} for col tx+32c ----
    // W chunk fill: warp ty handles rows ty*8..ty*8+7; lane tx cols {tx+32j}, j<4,
    // plus cols 128..131 from lanes tx<4 (130,131 are zero padding).
    float wreg[5][8];

    // prefetch chunk 0
    #pragma unroll
    for (int rr = 0; rr < 8; ++rr) {
        const float* wrow = W + (size_t)(ty * 8 + rr) * NO;
        #pragma unroll
        for (int j = 0; j < 4; ++j) wreg[j][rr] = wrow[tx + 32 * j];
        wreg[4][rr] = (tx < 2) ? wrow[tx + 128] : 0.f;
    }
    {   // store chunk 0 into buffer 0
        float2* Wb = Wt2;
        #pragma unroll
        for (int rr = 0; rr < 8; ++rr) {
            int kk = ty * 8 + rr;
            #pragma unroll
            for (int j = 0; j < 4; ++j)
                Wb[kk * 132 + tx + 32 * j] = make_float2(wreg[j][rr], wreg[j][rr]);
            if (tx < 4)
                Wb[kk * 132 + tx + 128] = make_float2(wreg[4][rr], wreg[4][rr]);
        }
    }
    __syncthreads();

    unsigned long long acc[5] = {0ull, 0ull, 0ull, 0ull, 0ull};
    const unsigned long long* arow_u = (const unsigned long long*)(xs2 + ty * 1024);

    for (int c = 0; c < 16; ++c) {
        if (c < 15) {   // prefetch chunk c+1 into regs (LDG latency overlaps compute)
            #pragma unroll
            for (int rr = 0; rr < 8; ++rr) {
                const float* wrow = W + (size_t)((c + 1) * 64 + ty * 8 + rr) * NO;
                #pragma unroll
                for (int j = 0; j < 4; ++j) wreg[j][rr] = wrow[tx + 32 * j];
                wreg[4][rr] = (tx < 2) ? wrow[tx + 128] : 0.f;
            }
        }
        const unsigned long long* Wb = (const unsigned long long*)(Wt2 + (c & 1) * WT2_F2);
        const unsigned long long* au = arow_u + c * 64;
        #pragma unroll 8
        for (int kk = 0; kk < 64; ++kk) {
            unsigned long long a = au[kk];
            const unsigned long long* wr = Wb + kk * 132 + tx;
            ffma2(acc[0], a, wr[0]);
            ffma2(acc[1], a, wr[32]);
            ffma2(acc[2], a, wr[64]);
            ffma2(acc[3], a, wr[96]);
            ffma2(acc[4], a, wr[128]);
        }
        if (c < 15) {   // store prefetched chunk into other buffer
            float2* Wb2 = Wt2 + ((c + 1) & 1) * WT2_F2;
            #pragma unroll
            for (int rr = 0; rr < 8; ++rr) {
                int kk = ty * 8 + rr;
                #pragma unroll
                for (int j = 0; j < 4; ++j)
                    Wb2[kk * 132 + tx + 32 * j] = make_float2(wreg[j][rr], wreg[j][rr]);
                if (tx < 4)
                    Wb2[kk * 132 + tx + 128] = make_float2(wreg[4][rr], wreg[4][rr]);
            }
        }
        __syncthreads();
    }

    #pragma unroll
    for (int cc = 0; cc < 5; ++cc) {
        int col = tx + 32 * cc;
        if (col < NO) {
            float lo, hi; unpack2(lo, hi, acc[cc]);
            float bv = bias[col];
            ps[ty * 132 + col]       = lo + bv;
            ps[(ty + 8) * 132 + col] = hi + bv;
        }
    }
    __syncthreads();

    // ---- derive damped-sinusoid params: 16 rows x 13 imus = 208 jobs ----
    if (tid < 16 * NI) {
        int il = tid / NI, m = tid - il * NI;
        int i = r0 + il;
        const float* p = ps + il * 132;
        float p0 = p[0 * 13 + m], p1 = p[1 * 13 + m];
        float p2 = p[2 * 13 + m], p3 = p[3 * 13 + m];
        float c   = p[4 * 13 + m], cth   = p[5 * 13 + m];
        float phi = p[6 * 13 + m], phith = p[7 * 13 + m];
        float nb  = p[8 * 13 + m], p9    = p[9 * 13 + m];

        out[m * S + i]          = minp[0] + nb;   // kin added later by k2
        out[NI * S + m * S + i] = sp(p9);         // noise_std

        float dh = 0.5f * sp(p1);
        float om = sqrtf(sp(p0));
        float e  = expf(-dh);
        float4 L;
        L.x = e * cosf(om);  L.y = e * sinf(om);
        L.z = c * cosf(phi); L.w = c * sinf(phi);
        float em = -expm1f(-dh);
        float tl = ceilf(logf(fmaxf(fabsf(c), 1e-30f) / (TAIL_EPS * em)) / dh);

        float dha = 0.5f * sp(p3);
        float oma = sqrtf(sp(p2));
        float ea  = expf(-dha);
        float4 A;
        A.x = ea * cosf(oma);    A.y = ea * sinf(oma);
        A.z = cth * cosf(phith); A.w = cth * sinf(phith);
        float ema = -expm1f(-dha);
        float ta = ceilf(logf(fmaxf(fabsf(cth), 1e-30f) / (TAIL_EPS * ema)) / dha);

        float tmax = fminf(fmaxf(fmaxf(tl, ta), 0.f), (float)S);
        g_lin[m * S + i]  = L;
        g_ang[m * S + i]  = A;
        g_tcut[m * S + i] = (int)tmax;
    }
}

// ---------------------------------------------------------------------------
// Kernel 2: warp-cooperative damped-sinusoid scatter, NO inner-loop atomics.
// grid (16 bands, 13 imus), 128 threads (4 warps). Warp w owns 32 sources
// i = band*128 + w*32 + ss, processed sequentially. For each source a 5-step
// shuffle product-scan builds T_l = state0 * R^lane per lane and R^32; each
// tile iteration writes 32 consecutive j's with plain LDS+FADD+STS into the
// warp's PRIVATE kin row (each address touched by exactly one lane within a
// source), then advances all lanes' T by R^32 (8 FFMA). __syncwarp orders the
// read-modify-writes across sources.
// ---------------------------------------------------------------------------
__global__ void __launch_bounds__(128, 2)
k2(float* __restrict__ out)
{
    __shared__ float kin[4][S];   // 32 KB, one private row per warp
    const int tid  = threadIdx.x;
    const int lane = tid & 31, w = tid >> 5;
    const int band = blockIdx.x, m = blockIdx.y;

    float4* kz = (float4*)&kin[0][0];
    for (int idx = tid; idx < 4 * S / 4; idx += 128) kz[idx] = make_float4(0.f, 0.f, 0.f, 0.f);
    __syncthreads();

    float* kw = kin[w];
    const int ibase = band * 128 + w * 32;

    for (int ss = 0; ss < 32; ++ss) {
        const int i  = ibase + ss;
        const int gi = m * S + i;
        const float4 L = g_lin[gi];
        const float4 A = g_ang[gi];
        const int   tc = g_tcut[gi];
        const int jend = min(S, i + tc + 1);

        // product scan: lane l -> R^(l+1)
        float clx = L.x, cly = L.y;
        float cax = A.x, cay = A.y;
        #pragma unroll
        for (int k = 1; k < 32; k <<= 1) {
            float olx = __shfl_up_sync(0xffffffffu, clx, k);
            float oly = __shfl_up_sync(0xffffffffu, cly, k);
            float oax = __shfl_up_sync(0xffffffffu, cax, k);
            float oay = __shfl_up_sync(0xffffffffu, cay, k);
            if (lane >= k) {
                float nlx = olx * clx - oly * cly;
                float nly = olx * cly + oly * clx;
                clx = nlx; cly = nly;
                float nax = oax * cax - oay * cay;
                float nay = oax * cay + oay * cax;
                cax = nax; cay = nay;
            }
        }
        const float r32lx = __shfl_sync(0xffffffffu, clx, 31);
        const float r32ly = __shfl_sync(0xffffffffu, cly, 31);
        const float r32ax = __shfl_sync(0xffffffffu, cax, 31);
        const float r32ay = __shfl_sync(0xffffffffu, cay, 31);

        // lane l needs R^l: shift down by one, lane 0 = identity
        float plx = __shfl_up_sync(0xffffffffu, clx, 1);
        float ply = __shfl_up_sync(0xffffffffu, cly, 1);
        float pax = __shfl_up_sync(0xffffffffu, cax, 1);
        float pay = __shfl_up_sync(0xffffffffu, cay, 1);
        if (lane == 0) { plx = 1.f; ply = 0.f; pax = 1.f; pay = 0.f; }

        // T_l = state0 * R^l
        float Tlx = L.z * plx - L.w * ply;
        float Tly = L.z * ply + L.w * plx;
        float Tax = A.z * pax - A.w * pay;
        float Tay = A.z * pay + A.w * pax;

        const int len = jend - i;              // >= 1
        const int nt  = (len + 31) >> 5;
        int j = i + lane;
        for (int it = 0; it < nt; ++it) {
            if (j < jend) kw[j] += Tly + Tay;
            float nlx = Tlx * r32lx - Tly * r32ly;
            float nly = Tlx * r32ly + Tly * r32lx;
            Tlx = nlx; Tly = nly;
            float nax = Tax * r32ax - Tay * r32ay;
            float nay = Tax * r32ay + Tay * r32ax;
            Tax = nax; Tay = nay;
            j += 32;
        }
        __syncwarp();
    }
    __syncthreads();

    // reduce 4 private rows, merge into out (cross-block via global atomics)
    float* orow = out + m * S;
    for (int jj = band * 128 + tid; jj < S; jj += 128) {
        float v = kin[0][jj] + kin[1][jj] + kin[2][jj] + kin[3][jj];
        atomicAdd(orow + jj, v);
    }
}

extern "C" void kernel_launch(void* const* d_in, const int* in_sizes, int n_in,
                              void* d_out, int out_size)
{
    const float* x     = (const float*)d_in[0];  // (1, 2048, 1024)
    const float* minp  = (const float*)d_in[1];  // (1,)
    const float* gamma = (const float*)d_in[2];  // (1024,)
    const float* beta  = (const float*)d_in[3];  // (1024,)
    const float* W     = (const float*)d_in[4];  // (1024, 130)
    const float* b     = (const float*)d_in[5];  // (130,)
    float* out = (float*)d_out;                  // (13,2048) out ++ (13,2048) noise_std

    cudaFuncSetAttribute(k1, cudaFuncAttributeMaxDynamicSharedMemorySize, K1_SMEM);

    k1<<<S / 16, dim3(32, 8), K1_SMEM>>>(x, minp, gamma, beta, W, b, out);
    k2<<<dim3(S / 128, NI), 128>>>(out);
}

// round 4
// speedup vs baseline: 3.4013x; 1.6984x over previous
#include <cuda_runtime.h>
#include <math.h>

#define S 2048
#define D 1024
#define NI 13
#define NO 130
#define LN_EPS 1e-5f
#define TAIL_EPS 1e-7f

// k1 smem: xs2 float2[8][1024] (64KB) overlapped by red float2[8][8][5][32] (80KB), ps after
#define RED_BYTES (8 * 8 * 5 * 32 * 8)          // 81920
#define K1_SMEM   (RED_BYTES + 16 * 132 * 4)    // 90368

// Scratch (allocation-free rule: __device__ globals)
__device__ float4 g_lin[NI * S];
__device__ float4 g_ang[NI * S];
__device__ int    g_tcut[NI * S];

__device__ __forceinline__ float sp(float x) {
    return (x > 0.f) ? x + log1pf(expf(-x)) : log1pf(expf(x));
}
__device__ __forceinline__ void ffma2(unsigned long long& acc,
                                      unsigned long long a, unsigned long long w) {
    asm("fma.rn.f32x2 %0, %1, %2, %0;" : "+l"(acc) : "l"(a), "l"(w));
}
__device__ __forceinline__ unsigned long long pk2(float v) {
    unsigned long long r;
    asm("mov.b64 %0, {%1, %1};" : "=l"(r) : "f"(v));
    return r;
}

// ---------------------------------------------------------------------------
// Kernel 1: fused LayerNorm + GEMM + parameter derivation.
// block (32,8)=256 threads, 16 rows/block, 128 blocks.
// Warp w computes ALL 8 row-pairs for k-slice [128w,128w+128): acc[8][5] f32x2.
// W read directly from L2 via coalesced LDG (no smem for W -> crossbar traffic
// drops ~11x vs R3); activations broadcast via LDS.128 (2 kk per load).
// ---------------------------------------------------------------------------
__global__ void __launch_bounds__(256, 1)
k1(const float* __restrict__ x, const float* __restrict__ minp,
   const float* __restrict__ gamma, const float* __restrict__ beta,
   const float* __restrict__ W, const float* __restrict__ bias,
   float* __restrict__ out)
{
    extern __shared__ char smraw[];
    float2* xs2 = (float2*)smraw;                 // [8 pairs][1024]
    float2* red = (float2*)smraw;                 // [8 warps][8 pairs][5][32] (reuses xs2)
    float*  ps  = (float*)(smraw + RED_BYTES);    // [16][132]

    const int tx = threadIdx.x, w = threadIdx.y;
    const int tid = w * 32 + tx;
    const int r0 = blockIdx.x * 16;

    // ---- LayerNorm stats for rows (r0+w, r0+w+8) ----
    const float4* xr0 = (const float4*)(x + (size_t)(r0 + w) * D);
    const float4* xr1 = (const float4*)(x + (size_t)(r0 + w + 8) * D);
    float s1 = 0.f, s2 = 0.f, u1 = 0.f, u2 = 0.f;
    #pragma unroll
    for (int it = 0; it < 8; ++it) {
        float4 a = xr0[it * 32 + tx];
        float4 b = xr1[it * 32 + tx];
        s1 += a.x + a.y + a.z + a.w;
        s2 += a.x * a.x + a.y * a.y + a.z * a.z + a.w * a.w;
        u1 += b.x + b.y + b.z + b.w;
        u2 += b.x * b.x + b.y * b.y + b.z * b.z + b.w * b.w;
    }
    #pragma unroll
    for (int o = 16; o; o >>= 1) {
        s1 += __shfl_xor_sync(0xffffffffu, s1, o);
        s2 += __shfl_xor_sync(0xffffffffu, s2, o);
        u1 += __shfl_xor_sync(0xffffffffu, u1, o);
        u2 += __shfl_xor_sync(0xffffffffu, u2, o);
    }
    const float mu0 = s1 * (1.f / D);
    const float rs0 = rsqrtf(s2 * (1.f / D) - mu0 * mu0 + LN_EPS);
    const float mu1 = u1 * (1.f / D);
    const float rs1 = rsqrtf(u2 * (1.f / D) - mu1 * mu1 + LN_EPS);

    // ---- normalize (second pass, L2-hot) and pack pair w ----
    const float4* g4p = (const float4*)gamma;
    const float4* b4p = (const float4*)beta;
    float2* xrow = xs2 + w * 1024;
    #pragma unroll
    for (int it = 0; it < 8; ++it) {
        int e = it * 32 + tx;
        float4 a = xr0[e], b = xr1[e];
        float4 g = g4p[e], be = b4p[e];
        int k = e * 4;
        xrow[k + 0] = make_float2((a.x - mu0) * rs0 * g.x + be.x, (b.x - mu1) * rs1 * g.x + be.x);
        xrow[k + 1] = make_float2((a.y - mu0) * rs0 * g.y + be.y, (b.y - mu1) * rs1 * g.y + be.y);
        xrow[k + 2] = make_float2((a.z - mu0) * rs0 * g.z + be.z, (b.z - mu1) * rs1 * g.z + be.z);
        xrow[k + 3] = make_float2((a.w - mu0) * rs0 * g.w + be.w, (b.w - mu1) * rs1 * g.w + be.w);
    }
    __syncthreads();

    // ---- GEMM: warp w, k in [128w, 128w+128), all 8 pairs, cols tx+32cg ----
    const int k0 = w * 128;
    unsigned long long acc[8][5];
    #pragma unroll
    for (int p = 0; p < 8; ++p)
        #pragma unroll
        for (int c = 0; c < 5; ++c) acc[p][c] = 0ull;

    float wv[2][2][5];   // [buf][kk-sub][colgroup]
    #pragma unroll
    for (int t = 0; t < 2; ++t) {
        const float* wr = W + (size_t)(k0 + t) * NO;
        #pragma unroll
        for (int cg = 0; cg < 4; ++cg) wv[0][t][cg] = wr[tx + 32 * cg];
        wv[0][t][4] = (tx < 2) ? wr[128 + tx] : 0.f;
    }

    const ulonglong2* xsu = (const ulonglong2*)xs2;   // [p*512 + k/2]
    const int kb = k0 >> 1;

    for (int st = 0; st < 64; ++st) {
        const int buf = st & 1;
        if (st < 63) {
            #pragma unroll
            for (int t = 0; t < 2; ++t) {
                const float* wr = W + (size_t)(k0 + 2 * (st + 1) + t) * NO;
                #pragma unroll
                for (int cg = 0; cg < 4; ++cg) wv[buf ^ 1][t][cg] = wr[tx + 32 * cg];
                wv[buf ^ 1][t][4] = (tx < 2) ? wr[128 + tx] : 0.f;
            }
        }
        ulonglong2 a2[8];
        #pragma unroll
        for (int p = 0; p < 8; ++p) a2[p] = xsu[p * 512 + kb + st];
        #pragma unroll
        for (int t = 0; t < 2; ++t) {
            #pragma unroll
            for (int cg = 0; cg < 5; ++cg) {
                unsigned long long wp = pk2(wv[buf][t][cg]);
                #pragma unroll
                for (int p = 0; p < 8; ++p)
                    ffma2(acc[p][cg], t ? a2[p].y : a2[p].x, wp);
            }
        }
    }
    __syncthreads();   // xs2 dead; red may now overwrite it

    // ---- cross-warp k-slice reduction through smem ----
    #pragma unroll
    for (int p = 0; p < 8; ++p)
        #pragma unroll
        for (int cg = 0; cg < 5; ++cg)
            red[((w * 8 + p) * 5 + cg) * 32 + tx] = *(float2*)&acc[p][cg];
    __syncthreads();

    for (int idx = tid; idx < 8 * 5 * 32; idx += 256) {
        int p = idx / 160, r = idx - p * 160;
        int cg = r >> 5, lane = r & 31, col = cg * 32 + lane;
        if (col < NO) {
            float sx = 0.f, sy = 0.f;
            #pragma unroll
            for (int ww = 0; ww < 8; ++ww) {
                float2 v = red[((ww * 8 + p) * 5 + cg) * 32 + lane];
                sx += v.x; sy += v.y;
            }
            float bv = bias[col];
            ps[p * 132 + col]       = sx + bv;
            ps[(p + 8) * 132 + col] = sy + bv;
        }
    }
    __syncthreads();

    // ---- derive damped-sinusoid params: 16 rows x 13 imus = 208 jobs ----
    if (tid < 16 * NI) {
        int il = tid / NI, m = tid - il * NI;
        int i = r0 + il;
        const float* p = ps + il * 132;
        float p0 = p[0 * 13 + m], p1 = p[1 * 13 + m];
        float p2 = p[2 * 13 + m], p3 = p[3 * 13 + m];
        float c   = p[4 * 13 + m], cth   = p[5 * 13 + m];
        float phi = p[6 * 13 + m], phith = p[7 * 13 + m];
        float nb  = p[8 * 13 + m], p9    = p[9 * 13 + m];

        out[m * S + i]          = minp[0] + nb;   // kin added later by k2
        out[NI * S + m * S + i] = sp(p9);         // noise_std

        float dh = 0.5f * sp(p1);
        float om = sqrtf(sp(p0));
        float e  = expf(-dh);
        float4 L;
        L.x = e * cosf(om);  L.y = e * sinf(om);
        L.z = c * cosf(phi); L.w = c * sinf(phi);
        float em = -expm1f(-dh);
        float tl = ceilf(logf(fmaxf(fabsf(c), 1e-30f) / (TAIL_EPS * em)) / dh);

        float dha = 0.5f * sp(p3);
        float oma = sqrtf(sp(p2));
        float ea  = expf(-dha);
        float4 A;
        A.x = ea * cosf(oma);    A.y = ea * sinf(oma);
        A.z = cth * cosf(phith); A.w = cth * sinf(phith);
        float ema = -expm1f(-dha);
        float ta = ceilf(logf(fmaxf(fabsf(cth), 1e-30f) / (TAIL_EPS * ema)) / dha);

        float tmax = fminf(fmaxf(fmaxf(tl, ta), 0.f), (float)S);
        g_lin[m * S + i]  = L;
        g_ang[m * S + i]  = A;
        g_tcut[m * S + i] = (int)tmax;
    }
}

// ---------------------------------------------------------------------------
// Kernel 2: warp-cooperative damped-sinusoid scatter, 2x unrolled (R^64 step).
// grid (32 bands, 13 imus), 128 threads (4 warps). Warp w owns 16 sources of
// its 64-source band; per source a shuffle product-scan builds per-lane
// T = state0*R^lane and R^32 -> R^64; lanes write j and j+32 per iteration
// into the warp's PRIVATE kin row, advancing two states by R^64.
// ---------------------------------------------------------------------------
__global__ void __launch_bounds__(128)
k2(float* __restrict__ out)
{
    __shared__ float kin[4][S];   // 32 KB, one private row per warp
    const int tid  = threadIdx.x;
    const int lane = tid & 31, w = tid >> 5;
    const int band = blockIdx.x, m = blockIdx.y;

    float4* kz = (float4*)&kin[0][0];
    for (int idx = tid; idx < 4 * S / 4; idx += 128) kz[idx] = make_float4(0.f, 0.f, 0.f, 0.f);
    __syncthreads();

    float* kw = kin[w];
    const int ibase = band * 64 + w * 16;

    for (int ss = 0; ss < 16; ++ss) {
        const int i  = ibase + ss;
        const int gi = m * S + i;
        const float4 L = g_lin[gi];
        const float4 A = g_ang[gi];
        const int   tc = g_tcut[gi];
        const int jend = min(S, i + tc + 1);

        // product scan: lane l -> R^(l+1)
        float clx = L.x, cly = L.y;
        float cax = A.x, cay = A.y;
        #pragma unroll
        for (int k = 1; k < 32; k <<= 1) {
            float olx = __shfl_up_sync(0xffffffffu, clx, k);
            float oly = __shfl_up_sync(0xffffffffu, cly, k);
            float oax = __shfl_up_sync(0xffffffffu, cax, k);
            float oay = __shfl_up_sync(0xffffffffu, cay, k);
            if (lane >= k) {
                float nlx = olx * clx - oly * cly;
                float nly = olx * cly + oly * clx;
                clx = nlx; cly = nly;
                float nax = oax * cax - oay * cay;
                float nay = oax * cay + oay * cax;
                cax = nax; cay = nay;
            }
        }
        const float r32lx = __shfl_sync(0xffffffffu, clx, 31);
        const float r32ly = __shfl_sync(0xffffffffu, cly, 31);
        const float r32ax = __shfl_sync(0xffffffffu, cax, 31);
        const float r32ay = __shfl_sync(0xffffffffu, cay, 31);
        // R^64 = (R^32)^2
        const float r64lx = r32lx * r32lx - r32ly * r32ly;
        const float r64ly = 2.f * r32lx * r32ly;
        const float r64ax = r32ax * r32ax - r32ay * r32ay;
        const float r64ay = 2.f * r32ax * r32ay;

        // lane l needs R^l: shift down by one, lane 0 = identity
        float plx = __shfl_up_sync(0xffffffffu, clx, 1);
        float ply = __shfl_up_sync(0xffffffffu, cly, 1);
        float pax = __shfl_up_sync(0xffffffffu, cax, 1);
        float pay = __shfl_up_sync(0xffffffffu, cay, 1);
        if (lane == 0) { plx = 1.f; ply = 0.f; pax = 1.f; pay = 0.f; }

        // Ta = state0 * R^l (offset 0); Tb = Ta * R^32 (offset 32)
        float Talx = L.z * plx - L.w * ply;
        float Taly = L.z * ply + L.w * plx;
        float Taax = A.z * pax - A.w * pay;
        float Taay = A.z * pay + A.w * pax;
        float Tblx = Talx * r32lx - Taly * r32ly;
        float Tbly = Talx * r32ly + Taly * r32lx;
        float Tbax = Taax * r32ax - Taay * r32ay;
        float Tbay = Taax * r32ay + Taay * r32ax;

        const int len = jend - i;              // >= 1
        const int nt  = (len + 63) >> 6;
        int j = i + lane;
        for (int it = 0; it < nt; ++it) {
            if (j      < jend) kw[j]      += Taly + Taay;
            if (j + 32 < jend) kw[j + 32] += Tbly + Tbay;
            float n0, n1;
            n0 = Talx * r64lx - Taly * r64ly; n1 = Talx * r64ly + Taly * r64lx;
            Talx = n0; Taly = n1;
            n0 = Taax * r64ax - Taay * r64ay; n1 = Taax * r64ay + Taay * r64ax;
            Taax = n0; Taay = n1;
            n0 = Tblx * r64lx - Tbly * r64ly; n1 = Tblx * r64ly + Tbly * r64lx;
            Tblx = n0; Tbly = n1;
            n0 = Tbax * r64ax - Tbay * r64ay; n1 = Tbax * r64ay + Tbay * r64ax;
            Tbax = n0; Tbay = n1;
            j += 64;
        }
        __syncwarp();
    }
    __syncthreads();

    // reduce 4 private rows, merge into out (cross-block via global atomics)
    float* orow = out + m * S;
    for (int jj = band * 64 + tid; jj < S; jj += 128) {
        float v = kin[0][jj] + kin[1][jj] + kin[2][jj] + kin[3][jj];
        atomicAdd(orow + jj, v);
    }
}

extern "C" void kernel_launch(void* const* d_in, const int* in_sizes, int n_in,
                              void* d_out, int out_size)
{
    const float* x     = (const float*)d_in[0];  // (1, 2048, 1024)
    const float* minp  = (const float*)d_in[1];  // (1,)
    const float* gamma = (const float*)d_in[2];  // (1024,)
    const float* beta  = (const float*)d_in[3];  // (1024,)
    const float* W     = (const float*)d_in[4];  // (1024, 130)
    const float* b     = (const float*)d_in[5];  // (130,)
    float* out = (float*)d_out;                  // (13,2048) out ++ (13,2048) noise_std

    cudaFuncSetAttribute(k1, cudaFuncAttributeMaxDynamicSharedMemorySize, K1_SMEM);

    k1<<<S / 16, dim3(32, 8), K1_SMEM>>>(x, minp, gamma, beta, W, b, out);
    k2<<<dim3(32, NI), 128>>>(out);
}